// round 5
// baseline (speedup 1.0000x reference)
#include <cuda_runtime.h>
#include <math.h>

#define NQ       12
#define DEPTH    4
#define DIM      4096
#define NTHREADS 256

typedef unsigned long long u64;

// ---- packed f32x2 helpers (validated in R2: compile + correct on sm_103a) ----
__device__ __forceinline__ u64 pk(float lo, float hi) {
    u64 r; asm("mov.b64 %0, {%1, %2};" : "=l"(r) : "f"(lo), "f"(hi)); return r;
}
__device__ __forceinline__ void upk(u64 v, float& lo, float& hi) {
    asm("mov.b64 {%0, %1}, %2;" : "=f"(lo), "=f"(hi) : "l"(v));
}
__device__ __forceinline__ u64 swp(u64 v) {
    float x, y; asm("mov.b64 {%0, %1}, %2;" : "=f"(x), "=f"(y) : "l"(v));
    u64 r; asm("mov.b64 %0, {%1, %2};" : "=l"(r) : "f"(y), "f"(x)); return r;
}
__device__ __forceinline__ u64 f2fma(u64 a, u64 b, u64 c) {
    u64 d; asm("fma.rn.f32x2 %0, %1, %2, %3;" : "=l"(d) : "l"(a), "l"(b), "l"(c)); return d;
}
__device__ __forceinline__ u64 f2mul(u64 a, u64 b) {
    u64 d; asm("mul.rn.f32x2 %0, %1, %2;" : "=l"(d) : "l"(a), "l"(b)); return d;
}

// XOR swizzle (R1, proven conflict-free) and closed-form CNOT gather (validated R3/R4)
__device__ __forceinline__ int swz(int e) { return e ^ ((e >> 4) & 15); }
__device__ __forceinline__ int gperm(int j) {
    return j ^ (j >> 1) ^ ((j & 1) ? 0xC00 : 0);
}

// Lane-parallel gate on register bit k (k=0..2). Pack lane = reg bit 3.
// g: ar0..ar3 (broadcast u00r,u01r,u10r,u11r), ai0..ai3 (+ui), ni0..ni3 (-ui).
__device__ __forceinline__ void pgate(u64 Pr[8], u64 Pi[8], const u64* __restrict__ g, int k) {
    const u64 ar0 = g[0], ar1 = g[1], ar2 = g[2], ar3 = g[3];
    const u64 ai0 = g[4], ai1 = g[5], ai2 = g[6], ai3 = g[7];
    const u64 ni0 = g[8], ni1 = g[9], ni2 = g[10], ni3 = g[11];
    const int m = 1 << k;
    #pragma unroll
    for (int j0 = 0; j0 < 8; ++j0) {
        if (j0 & m) continue;
        const int j1 = j0 | m;
        const u64 p0r = Pr[j0], p0i = Pi[j0], p1r = Pr[j1], p1i = Pi[j1];
        Pr[j0] = f2fma(ar0, p0r, f2fma(ni0, p0i, f2fma(ar1, p1r, f2mul(ni1, p1i))));
        Pi[j0] = f2fma(ar0, p0i, f2fma(ai0, p0r, f2fma(ar1, p1i, f2mul(ai1, p1r))));
        Pr[j1] = f2fma(ar2, p0r, f2fma(ni2, p0i, f2fma(ar3, p1r, f2mul(ni3, p1i))));
        Pi[j1] = f2fma(ar2, p0i, f2fma(ai2, p0r, f2fma(ar3, p1i, f2mul(ai3, p1r))));
    }
}

// Lane-parallel gate, purely real input state (layer 0 first gate).
__device__ __forceinline__ void pgate_real(u64 Pr[8], u64 Pi[8], const u64* __restrict__ g, int k) {
    const u64 ar0 = g[0], ar1 = g[1], ar2 = g[2], ar3 = g[3];
    const u64 ai0 = g[4], ai1 = g[5], ai2 = g[6], ai3 = g[7];
    const int m = 1 << k;
    #pragma unroll
    for (int j0 = 0; j0 < 8; ++j0) {
        if (j0 & m) continue;
        const int j1 = j0 | m;
        const u64 p0r = Pr[j0], p1r = Pr[j1];
        Pr[j0] = f2fma(ar0, p0r, f2mul(ar1, p1r));
        Pi[j0] = f2fma(ai0, p0r, f2mul(ai1, p1r));
        Pr[j1] = f2fma(ar2, p0r, f2mul(ar3, p1r));
        Pi[j1] = f2fma(ai2, p0r, f2mul(ai3, p1r));
    }
}

// Gate on the pack bit (reg bit 3): lanes of each u64 are the gate pair.
// g: C1=(u00r,u11r) C2=(u01r,u10r) C3=(-u00i,-u11i) C4=(-u01i,-u10i) C5=(u00i,u11i) C6=(u01i,u10i)
__device__ __forceinline__ void sgate(u64 Pr[8], u64 Pi[8], const u64* __restrict__ g) {
    const u64 C1 = g[0], C2 = g[1], C3 = g[2], C4 = g[3], C5 = g[4], C6 = g[5];
    #pragma unroll
    for (int j = 0; j < 8; ++j) {
        const u64 pr = Pr[j], pi = Pi[j];
        const u64 prs = swp(pr), pis = swp(pi);
        Pr[j] = f2fma(C1, pr, f2fma(C2, prs, f2fma(C3, pi, f2mul(C4, pis))));
        Pi[j] = f2fma(C1, pi, f2fma(C2, pis, f2fma(C5, pr, f2mul(C6, prs))));
    }
}

__global__ void __launch_bounds__(NTHREADS, 2)
qsim_kernel(const float* __restrict__ input,
            const float* __restrict__ ax,
            const float* __restrict__ ay,
            const float* __restrict__ az,
            float* __restrict__ out)
{
    __shared__ float2 sAmp[DIM];                 // 32 KB exchange buffer (static!)
    __shared__ u64    sG[DEPTH * NQ * 12];       // 48 gates x 12 packed coeffs = 4.5 KB
    __shared__ float  sRed[16];

    const int t   = threadIdx.x;
    const int row = blockIdx.x;

    // ---- fused gate matrices U = Rz * Ry * Rx, prebroadcast packed coeffs ----
    if (t < DEPTH * NQ) {
        float sx, cx, sy, cy, sz, cz;
        sincosf(0.5f * ax[t], &sx, &cx);
        sincosf(0.5f * ay[t], &sy, &cy);
        sincosf(0.5f * az[t], &sz, &cz);
        const float m00r = cy * cx, m00i =  sy * sx;
        const float m01r = -sy * cx, m01i = -cy * sx;
        const float m10r =  sy * cx, m10i = -cy * sx;
        const float m11r =  cy * cx, m11i = -sy * sx;
        const float u00r = cz * m00r + sz * m00i, u00i = cz * m00i - sz * m00r;
        const float u01r = cz * m01r + sz * m01i, u01i = cz * m01i - sz * m01r;
        const float u10r = cz * m10r - sz * m10i, u10i = cz * m10i + sz * m10r;
        const float u11r = cz * m11r - sz * m11i, u11i = cz * m11i + sz * m11r;
        u64* g = &sG[t * 12];
        if ((t & 3) == 0) {
            // swap-form gate (qubits 0,4,8): lane-tailored coefficient vectors
            g[0] = pk(u00r, u11r);  g[1] = pk(u01r, u10r);
            g[2] = pk(-u00i, -u11i); g[3] = pk(-u01i, -u10i);
            g[4] = pk(u00i, u11i);  g[5] = pk(u01i, u10i);
        } else {
            // lane-parallel gate: broadcast coefficients
            g[0]  = pk(u00r, u00r);  g[1]  = pk(u01r, u01r);
            g[2]  = pk(u10r, u10r);  g[3]  = pk(u11r, u11r);
            g[4]  = pk(u00i, u00i);  g[5]  = pk(u01i, u01i);
            g[6]  = pk(u10i, u10i);  g[7]  = pk(u11i, u11i);
            g[8]  = pk(-u00i, -u00i); g[9]  = pk(-u01i, -u01i);
            g[10] = pk(-u10i, -u10i); g[11] = pk(-u11i, -u11i);
        }
    }

    // ---- load input row + amplitude encoding ----
    float mag[16];
    const float4* inrow = reinterpret_cast<const float4*>(input + (size_t)row * DIM);
    float s1 = 0.f, s2 = 0.f;
    #pragma unroll
    for (int k = 0; k < 4; ++k) {
        const float4 v = inrow[t * 4 + k];
        const float a = fabsf(v.x), b = fabsf(v.y), c = fabsf(v.z), d = fabsf(v.w);
        mag[4 * k + 0] = a; mag[4 * k + 1] = b;
        mag[4 * k + 2] = c; mag[4 * k + 3] = d;
        s1 += (a + b) + (c + d);
        s2 += a * a + b * b + c * c + d * d;
    }
    #pragma unroll
    for (int o = 16; o > 0; o >>= 1) {
        s1 += __shfl_xor_sync(0xffffffffu, s1, o);
        s2 += __shfl_xor_sync(0xffffffffu, s2, o);
    }
    if ((t & 31) == 0) { sRed[t >> 5] = s1; sRed[8 + (t >> 5)] = s2; }
    __syncthreads();   // also publishes sG
    float S1 = 0.f, S2 = 0.f;
    #pragma unroll
    for (int w = 0; w < 8; ++w) { S1 += sRed[w]; S2 += sRed[8 + w]; }

    // ---- packed state: Pr[j] = (re[j], re[j+8]), Pi[j] = (im[j], im[j+8]) ----
    // flat index = (t<<4)|r, reg bit 3 = pack lane.
    u64 Pr[8], Pi[8];
    if (S1 > 1e-8f) {
        const float sc   = rsqrtf(S1);
        const float norm = sqrtf(S2) * sc;
        const float fs   = (norm > 1e-8f) ? (sc / norm) : sc;
        #pragma unroll
        for (int j = 0; j < 8; ++j) {
            Pr[j] = pk(mag[j] * fs, mag[j + 8] * fs);
            Pi[j] = pk(0.f, 0.f);
        }
    } else {
        #pragma unroll
        for (int j = 0; j < 8; ++j) { Pr[j] = pk(0.015625f, 0.015625f); Pi[j] = pk(0.f, 0.f); }
    }

    const int base1 = ((t >> 4) << 8) | (t & 15);

    #pragma unroll 1
    for (int layer = 0; layer < DEPTH; ++layer) {
        const u64* gl = &sG[layer * NQ * 12];

        // ---- Stage A (L0: reg bit k = global bit k -> qubit 11-k; pack bit -> qubit 8) ----
        if (layer == 0) pgate_real(Pr, Pi, gl + 11 * 12, 0);
        else            pgate     (Pr, Pi, gl + 11 * 12, 0);
        pgate(Pr, Pi, gl + 10 * 12, 1);
        pgate(Pr, Pi, gl +  9 * 12, 2);
        sgate(Pr, Pi, gl +  8 * 12);

        // ---- E1: L0 -> L1 ----
        __syncthreads();
        #pragma unroll
        for (int j = 0; j < 8; ++j) {
            float rl, rh, il, ih;
            upk(Pr[j], rl, rh); upk(Pi[j], il, ih);
            sAmp[swz((t << 4) | j)]       = make_float2(rl, il);
            sAmp[swz((t << 4) | (j + 8))] = make_float2(rh, ih);
        }
        __syncthreads();
        #pragma unroll
        for (int j = 0; j < 8; ++j) {
            const float2 a = sAmp[swz(base1 | (j << 4))];
            const float2 b = sAmp[swz(base1 | ((j + 8) << 4))];
            Pr[j] = pk(a.x, b.x); Pi[j] = pk(a.y, b.y);
        }

        // ---- Stage B (L1: reg bit k = global bit 4+k -> qubit 7-k; pack bit -> qubit 4) ----
        pgate(Pr, Pi, gl + 7 * 12, 0);
        pgate(Pr, Pi, gl + 6 * 12, 1);
        pgate(Pr, Pi, gl + 5 * 12, 2);
        sgate(Pr, Pi, gl + 4 * 12);

        // ---- E2: L1 -> L2 ----
        __syncthreads();
        #pragma unroll
        for (int j = 0; j < 8; ++j) {
            float rl, rh, il, ih;
            upk(Pr[j], rl, rh); upk(Pi[j], il, ih);
            sAmp[swz(base1 | (j << 4))]       = make_float2(rl, il);
            sAmp[swz(base1 | ((j + 8) << 4))] = make_float2(rh, ih);
        }
        __syncthreads();
        #pragma unroll
        for (int j = 0; j < 8; ++j) {
            const float2 a = sAmp[swz((j << 8) | t)];
            const float2 b = sAmp[swz(((j + 8) << 8) | t)];
            Pr[j] = pk(a.x, b.x); Pi[j] = pk(a.y, b.y);
        }

        // ---- Stage C (L2: reg bit k = global bit 8+k -> qubit 3-k; pack bit -> qubit 0) ----
        pgate(Pr, Pi, gl + 3 * 12, 0);
        pgate(Pr, Pi, gl + 2 * 12, 1);
        pgate(Pr, Pi, gl + 1 * 12, 2);
        sgate(Pr, Pi, gl + 0 * 12);

        // ---- E3: L2 -> L0 with CNOT ladder folded into the gather ----
        __syncthreads();
        #pragma unroll
        for (int j = 0; j < 8; ++j) {
            float rl, rh, il, ih;
            upk(Pr[j], rl, rh); upk(Pi[j], il, ih);
            sAmp[swz((j << 8) | t)]       = make_float2(rl, il);
            sAmp[swz(((j + 8) << 8) | t)] = make_float2(rh, ih);
        }
        __syncthreads();
        #pragma unroll
        for (int j = 0; j < 8; ++j) {
            const float2 a = sAmp[swz(gperm((t << 4) | j))];
            const float2 b = sAmp[swz(gperm((t << 4) | (j + 8)))];
            Pr[j] = pk(a.x, b.x); Pi[j] = pk(a.y, b.y);
        }
    }

    // ---- measurement: |amplitude| ----
    float m16[16];
    #pragma unroll
    for (int j = 0; j < 8; ++j) {
        float rl, rh, il, ih;
        upk(Pr[j], rl, rh); upk(Pi[j], il, ih);
        m16[j]     = sqrtf(rl * rl + il * il);
        m16[j + 8] = sqrtf(rh * rh + ih * ih);
    }
    float4* orow = reinterpret_cast<float4*>(out + (size_t)row * DIM);
    #pragma unroll
    for (int k = 0; k < 4; ++k)
        orow[t * 4 + k] = make_float4(m16[4 * k + 0], m16[4 * k + 1],
                                      m16[4 * k + 2], m16[4 * k + 3]);
}

extern "C" void kernel_launch(void* const* d_in, const int* in_sizes, int n_in,
                              void* d_out, int out_size) {
    const float* input = (const float*)d_in[0];
    const float* ax    = (const float*)d_in[1];
    const float* ay    = (const float*)d_in[2];
    const float* az    = (const float*)d_in[3];
    float* out = (float*)d_out;
    const int rows = in_sizes[0] / DIM;
    qsim_kernel<<<rows, NTHREADS>>>(input, ax, ay, az, out);
}

// round 6
// speedup vs baseline: 1.0932x; 1.0932x over previous
#include <cuda_runtime.h>
#include <math.h>

#define NQ       12
#define DEPTH    4
#define DIM      4096
#define NTHREADS 256

// XOR swizzle for conflict-free float2 shared accesses (R1-proven)
__device__ __forceinline__ int swz(int e) { return e ^ ((e >> 4) & 15); }

// Closed-form composed CNOT-ladder gather (validated R3/R4): s_after[i] = s_before[gperm(i)]
__device__ __forceinline__ int gperm(int j) {
    return j ^ (j >> 1) ^ ((j & 1) ? 0xC00 : 0);
}

// Fused 2x2 complex gate on register-local bit k of the 16-amp register file.
__device__ __forceinline__ void apply_gate(float re[16], float im[16],
                                           const float* __restrict__ g, int k) {
    const float u00r = g[0], u00i = g[1], u01r = g[2], u01i = g[3];
    const float u10r = g[4], u10i = g[5], u11r = g[6], u11i = g[7];
    const int m = 1 << k;
    #pragma unroll
    for (int r0 = 0; r0 < 16; ++r0) {
        if (r0 & m) continue;
        const int r1 = r0 | m;
        const float a0r = re[r0], a0i = im[r0];
        const float a1r = re[r1], a1i = im[r1];
        re[r0] = u00r * a0r - u00i * a0i + u01r * a1r - u01i * a1i;
        im[r0] = u00r * a0i + u00i * a0r + u01r * a1i + u01i * a1r;
        re[r1] = u10r * a0r - u10i * a0i + u11r * a1r - u11i * a1i;
        im[r1] = u10r * a0i + u10i * a0r + u11r * a1i + u11i * a1r;
    }
}

// Same gate, purely real input state (layer 0 first gate): half the FMAs.
__device__ __forceinline__ void apply_gate_real(float re[16], float im[16],
                                                const float* __restrict__ g, int k) {
    const float u00r = g[0], u00i = g[1], u01r = g[2], u01i = g[3];
    const float u10r = g[4], u10i = g[5], u11r = g[6], u11i = g[7];
    const int m = 1 << k;
    #pragma unroll
    for (int r0 = 0; r0 < 16; ++r0) {
        if (r0 & m) continue;
        const int r1 = r0 | m;
        const float a0r = re[r0], a1r = re[r1];
        re[r0] = u00r * a0r + u01r * a1r;
        im[r0] = u00i * a0r + u01i * a1r;
        re[r1] = u10r * a0r + u11r * a1r;
        im[r1] = u10i * a0r + u11i * a1r;
    }
}

__global__ void __launch_bounds__(NTHREADS, 2)
qsim_kernel(const float* __restrict__ input,
            const float* __restrict__ ax,
            const float* __restrict__ ay,
            const float* __restrict__ az,
            float* __restrict__ out)
{
    // 3 rotating exchange buffers: E1 -> sB[0..DIM), E2 -> sB[DIM..2*DIM), E3 -> sB[2*DIM..3*DIM).
    // A buffer written in layer l was last read in layer l-1 with >=2 barriers in between,
    // so no write-protect barrier is ever needed: exactly one bar per exchange.
    extern __shared__ float2 sB[];

    __shared__ float sGates[DEPTH * NQ * 8];  // 48 fused gates
    __shared__ float sRed[16];

    const int t   = threadIdx.x;
    const int row = blockIdx.x;

    // ---- fused gate matrices U = Rz * Ry * Rx ----
    if (t < DEPTH * NQ) {
        float sx, cx, sy, cy, sz, cz;
        sincosf(0.5f * ax[t], &sx, &cx);
        sincosf(0.5f * ay[t], &sy, &cy);
        sincosf(0.5f * az[t], &sz, &cz);
        const float m00r = cy * cx, m00i =  sy * sx;
        const float m01r = -sy * cx, m01i = -cy * sx;
        const float m10r =  sy * cx, m10i = -cy * sx;
        const float m11r =  cy * cx, m11i = -sy * sx;
        float* g = &sGates[t * 8];
        g[0] = cz * m00r + sz * m00i;  g[1] = cz * m00i - sz * m00r;
        g[2] = cz * m01r + sz * m01i;  g[3] = cz * m01i - sz * m01r;
        g[4] = cz * m10r - sz * m10i;  g[5] = cz * m10i + sz * m10r;
        g[6] = cz * m11r - sz * m11i;  g[7] = cz * m11i + sz * m11r;
    }

    // ---- load input row + amplitude encoding ----
    float mag[16];
    const float4* inrow = reinterpret_cast<const float4*>(input + (size_t)row * DIM);
    float s1 = 0.f, s2 = 0.f;
    #pragma unroll
    for (int k = 0; k < 4; ++k) {
        const float4 v = inrow[t * 4 + k];
        const float a = fabsf(v.x), b = fabsf(v.y), c = fabsf(v.z), d = fabsf(v.w);
        mag[4 * k + 0] = a; mag[4 * k + 1] = b;
        mag[4 * k + 2] = c; mag[4 * k + 3] = d;
        s1 += (a + b) + (c + d);
        s2 += a * a + b * b + c * c + d * d;
    }
    #pragma unroll
    for (int o = 16; o > 0; o >>= 1) {
        s1 += __shfl_xor_sync(0xffffffffu, s1, o);
        s2 += __shfl_xor_sync(0xffffffffu, s2, o);
    }
    if ((t & 31) == 0) { sRed[t >> 5] = s1; sRed[8 + (t >> 5)] = s2; }
    __syncthreads();   // also publishes sGates
    float S1 = 0.f, S2 = 0.f;
    #pragma unroll
    for (int w = 0; w < 8; ++w) { S1 += sRed[w]; S2 += sRed[8 + w]; }

    // state: thread t holds flat indices [t*16, t*16+16) (Layout0)
    float re[16], im[16];
    if (S1 > 1e-8f) {
        const float sc   = rsqrtf(S1);
        const float norm = sqrtf(S2) * sc;
        const float fs   = (norm > 1e-8f) ? (sc / norm) : sc;
        #pragma unroll
        for (int r = 0; r < 16; ++r) { re[r] = mag[r] * fs; im[r] = 0.f; }
    } else {
        #pragma unroll
        for (int r = 0; r < 16; ++r) { re[r] = 0.015625f; im[r] = 0.f; }
    }

    const int base1 = ((t >> 4) << 8) | (t & 15);

    #pragma unroll 1
    for (int layer = 0; layer < DEPTH; ++layer) {
        const float* gl = &sGates[layer * NQ * 8];

        // ---- Stage A (L0): reg bit k = global bit k -> qubit 11-k ----
        if (layer == 0) {
            apply_gate_real(re, im, gl + 11 * 8, 0);     // state purely real at entry
            apply_gate(re, im, gl + 10 * 8, 1);
            apply_gate(re, im, gl +  9 * 8, 2);
            apply_gate(re, im, gl +  8 * 8, 3);
        } else {
            #pragma unroll
            for (int k = 0; k < 4; ++k) apply_gate(re, im, gl + (11 - k) * 8, k);
        }

        // ---- E1: L0 -> L1 (buffer 0) ----
        #pragma unroll
        for (int r = 0; r < 16; ++r)
            sB[swz((t << 4) | r)] = make_float2(re[r], im[r]);
        __syncthreads();
        #pragma unroll
        for (int r = 0; r < 16; ++r) {
            const float2 v = sB[swz(base1 | (r << 4))];
            re[r] = v.x; im[r] = v.y;
        }

        // ---- Stage B (L1): reg bit k = global bit 4+k -> qubit 7-k ----
        #pragma unroll
        for (int k = 0; k < 4; ++k) apply_gate(re, im, gl + (7 - k) * 8, k);

        // ---- E2: L1 -> L2 (buffer 1) ----
        #pragma unroll
        for (int r = 0; r < 16; ++r)
            sB[DIM + swz(base1 | (r << 4))] = make_float2(re[r], im[r]);
        __syncthreads();
        #pragma unroll
        for (int r = 0; r < 16; ++r) {
            const float2 v = sB[DIM + swz((r << 8) | t)];
            re[r] = v.x; im[r] = v.y;
        }

        // ---- Stage C (L2): reg bit k = global bit 8+k -> qubit 3-k ----
        #pragma unroll
        for (int k = 0; k < 4; ++k) apply_gate(re, im, gl + (3 - k) * 8, k);

        // ---- E3 (layers 0-2): L2 -> L0 with CNOT ladder folded in (buffer 2) ----
        if (layer < DEPTH - 1) {
            #pragma unroll
            for (int r = 0; r < 16; ++r)
                sB[2 * DIM + swz((r << 8) | t)] = make_float2(re[r], im[r]);
            __syncthreads();
            #pragma unroll
            for (int r = 0; r < 16; ++r) {
                const float2 v = sB[2 * DIM + swz(gperm((t << 4) | r))];
                re[r] = v.x; im[r] = v.y;
            }
        }
    }

    // ---- epilogue: layer 3's CNOT ladder folded into the output scatter ----
    // Thread holds s_before[j] at j = (r<<8)|t (L2 layout). out[i] = |s_before[gperm(i)]|,
    // so i = G^{-1}(j):  p = parity(j);  h = j ^ (p?0xC00:0);  i = graydecode(h).
    float* orow = out + (size_t)row * DIM;
    const int pt = __popc(t) & 1;
    #pragma unroll
    for (int r = 0; r < 16; ++r) {
        const int j = (r << 8) | t;
        const int p = (__popc(r) & 1) ^ pt;
        int i = j ^ (p ? 0xC00 : 0);
        i ^= i >> 1; i ^= i >> 2; i ^= i >> 4; i ^= i >> 8;
        orow[i] = sqrtf(re[r] * re[r] + im[r] * im[r]);
    }
}

extern "C" void kernel_launch(void* const* d_in, const int* in_sizes, int n_in,
                              void* d_out, int out_size) {
    const float* input = (const float*)d_in[0];
    const float* ax    = (const float*)d_in[1];
    const float* ay    = (const float*)d_in[2];
    const float* az    = (const float*)d_in[3];
    float* out = (float*)d_out;
    const int rows = in_sizes[0] / DIM;
    const int smem = 3 * DIM * sizeof(float2);  // 96 KB rotating exchange buffers
    cudaFuncSetAttribute(qsim_kernel, cudaFuncAttributeMaxDynamicSharedMemorySize, smem);
    qsim_kernel<<<rows, NTHREADS, smem>>>(input, ax, ay, az, out);
}